// round 15
// baseline (speedup 1.0000x reference)
#include <cuda_runtime.h>
#include <cuda_bf16.h>

// Problem constants:
//   N events, H=256, W=336, B=8, C=9, HID=100
//   out: [B, 2C, H, W] float32
//   out idx = x + W*y + W*H*i + W*H*C*p01 + 2*W*H*C*b
#define HID        100
#define C_BINS     9
#define W_DIM      336
#define H_DIM      256
#define WH         (W_DIM * H_DIM)          // 86016
#define WHC        (WH * C_BINS)            // 774144
#define WHC2       (2 * WHC)                // 1548288
#define NCELLS     (16 * WH)                // (2b+p01) in [0,16) x pixel

// LUT over s in [-1,1]: 1025 knots, step 2/1024. Bin shift 0.125 = 64 steps.
#define LUT_SIZE     1025
#define LUT_SCALE    512.0f
#define BIN_STEP_IDX 64

#define LUT_THREADS  256
#define LUT_EPB      8                       // entries per block (4 iters x 2)
#define LUT_BLOCKS   129                     // 129*8 = 1032 >= 1025

// Single scratch region (one memset): [A: NCELLS float4][B: NCELLS float4][S: NCELLS float]
#define SCRATCH_F4   (2 * NCELLS)            // float4 count for A+B
__device__ float4 g_scratch[SCRATCH_F4 + NCELLS / 4 + 1];   // ~49.6 MB
__device__ float  g_lut[LUT_SIZE];

#define SA (g_scratch)
#define SB (g_scratch + NCELLS)
#define SS (reinterpret_cast<float*>(g_scratch + SCRATCH_F4))

__device__ __forceinline__ float leaky(float v) {
    return v >= 0.0f ? v : 0.1f * v;
}

// LUT build: smem-staged weights + k-split warps, 8 entries per block.
// Stage once (coalesced), then 4 iterations of {2 entries x 4 k-chunk warps},
// each warp covering 25 of the 100 (linear) layer-2 k-terms via LDS.
__global__ void __launch_bounds__(LUT_THREADS)
lut_kernel(const float* __restrict__ w1, const float* __restrict__ b1,
           const float* __restrict__ w2, const float* __restrict__ b2,
           const float* __restrict__ w3, const float* __restrict__ b3) {
    __shared__ float4 s_w2[25 * HID];        // w2[k][j], 25 float4 per k row
    __shared__ float4 s_b2[25], s_w3[25];
    __shared__ float  s_w1[HID], s_b1[HID];
    __shared__ float4 sm_a[2][4][25];

    const int tid  = threadIdx.x;
    const int lane = tid & 31;
    const int w    = tid >> 5;               // warp 0..7
    const int slot = w >> 2;                 // entry slot 0..1
    const int c    = w & 3;                  // k-chunk 0..3
    const int koff = 25 * c;
    const int jl   = (lane < 25) ? lane : 24;

    // ---- stage weights (one coalesced pass) ----
    {
        const float4* w2v = (const float4*)w2;
        for (int i = tid; i < 25 * HID; i += LUT_THREADS)
            s_w2[i] = __ldg(w2v + i);
        if (tid < 25) {
            s_b2[tid] = __ldg((const float4*)b2 + tid);
            s_w3[tid] = __ldg((const float4*)w3 + tid);
        }
        if (tid < HID) {
            s_w1[tid] = __ldg(w1 + tid);
            s_b1[tid] = __ldg(b1 + tid);
        }
    }
    const float b3v = __ldg(b3);
    __syncthreads();

#pragma unroll
    for (int it = 0; it < 4; ++it) {
        int entry = blockIdx.x * LUT_EPB + it * 2 + slot;
        if (entry > LUT_SIZE - 1) entry = LUT_SIZE - 1;   // dup work, benign

        const float s = -1.0f + (float)entry * (2.0f / 1024.0f);

        // lanes 0..24: h1 for one k in this warp's chunk
        float h_l = 0.0f;
        if (lane < 25)
            h_l = leaky(fmaf(s, s_w1[koff + lane], s_b1[koff + lane]));

        // each lane: 4 output columns j = 4*jl..4*jl+3 over this chunk's 25 k
        float4 a = make_float4(0.f, 0.f, 0.f, 0.f);
#pragma unroll
        for (int m = 0; m < 25; ++m) {
            float h = __shfl_sync(0xffffffffu, h_l, m);
            float4 wv = s_w2[(koff + m) * 25 + jl];
            a.x = fmaf(h, wv.x, a.x);
            a.y = fmaf(h, wv.y, a.y);
            a.z = fmaf(h, wv.z, a.z);
            a.w = fmaf(h, wv.w, a.w);
        }

        if (lane < 25)
            sm_a[slot][c][lane] = a;
        __syncthreads();

        // finalize: one warp per entry (chunk-0 warps)
        if (c == 0) {
            float acc = 0.0f;
            if (lane < 25) {
                float4 a0 = sm_a[slot][0][lane];
                float4 a1 = sm_a[slot][1][lane];
                float4 a2 = sm_a[slot][2][lane];
                float4 a3 = sm_a[slot][3][lane];
                float4 bb = s_b2[lane];
                float4 t;
                t.x = a0.x + a1.x + a2.x + a3.x + bb.x;
                t.y = a0.y + a1.y + a2.y + a3.y + bb.y;
                t.z = a0.z + a1.z + a2.z + a3.z + bb.z;
                t.w = a0.w + a1.w + a2.w + a3.w + bb.w;
                float4 w3v = s_w3[lane];
                acc  = w3v.x * leaky(t.x);
                acc += w3v.y * leaky(t.y);
                acc += w3v.z * leaky(t.z);
                acc += w3v.w * leaky(t.w);
            }
            acc += __shfl_xor_sync(0xffffffffu, acc, 16);
            acc += __shfl_xor_sync(0xffffffffu, acc, 8);
            acc += __shfl_xor_sync(0xffffffffu, acc, 4);
            acc += __shfl_xor_sync(0xffffffffu, acc, 2);
            acc += __shfl_xor_sync(0xffffffffu, acc, 1);
            if (lane == 0)
                g_lut[entry] = acc + b3v;
        }
        __syncthreads();   // protect sm_a before next iteration overwrites
    }
}

// Scatter into SoA scratch: red.v4 (bins 0-3) + red.v4 (bins 4-7) + red (bin 8).
// Event loads use ld.global.cs (evict-first) so the 40 MB event stream does
// not evict the L2-resident scratch lines the REDs RMW against.
__global__ void __launch_bounds__(256)
scatter_kernel(const float* __restrict__ ev, int N) {
    int n = blockIdx.x * blockDim.x + threadIdx.x;
    if (n >= N) return;

    const float* e = ev + 5ll * n;
    float xf = __ldcs(e + 0), yf = __ldcs(e + 1), t = __ldcs(e + 2);
    float pf = __ldcs(e + 3), bf = __ldcs(e + 4);

    int p01  = (pf > 0.0f) ? 1 : 0;
    int cell = ((int)bf * 2 + p01) * WH + (int)xf + W_DIM * (int)yf;

    float u0 = fmaf(t, LUT_SCALE, LUT_SCALE);
    int   i0 = (int)u0;
    if (i0 > LUT_SIZE - 2) i0 = LUT_SIZE - 2;
    float fr = u0 - (float)i0;

    float v[C_BINS];
#pragma unroll
    for (int i = 0; i < C_BINS; ++i) {
        int base = i0 - BIN_STEP_IDX * i;
        float v0 = g_lut[base];
        float v1 = g_lut[base + 1];
        v[i] = t * fmaf(fr, v1 - v0, v0);
    }

    asm volatile("red.global.add.v4.f32 [%0], {%1,%2,%3,%4};"
                 :: "l"(SA + cell), "f"(v[0]), "f"(v[1]), "f"(v[2]), "f"(v[3])
                 : "memory");
    asm volatile("red.global.add.v4.f32 [%0], {%1,%2,%3,%4};"
                 :: "l"(SB + cell), "f"(v[4]), "f"(v[5]), "f"(v[6]), "f"(v[7])
                 : "memory");
    atomicAdd(SS + cell, v[8]);
}

// Transpose SoA scratch -> reference output layout. Read-once scratch via
// ld.global.cs; out stores via st.global.cs (no L2 allocate churn).
__global__ void __launch_bounds__(256)
transpose_kernel(float* __restrict__ out) {
    int c = blockIdx.x * blockDim.x + threadIdx.x;
    if (c >= NCELLS) return;

    int q  = c % WH;
    int pb = c / WH;                 // 2*b + p01
    float4 a = __ldcs(SA + c);
    float4 b = __ldcs(SB + c);
    float  v8 = __ldcs(SS + c);

    float* o = out + q + (pb & 1) * WHC + (pb >> 1) * WHC2;
    __stcs(o + 0 * WH, a.x);  __stcs(o + 1 * WH, a.y);
    __stcs(o + 2 * WH, a.z);  __stcs(o + 3 * WH, a.w);
    __stcs(o + 4 * WH, b.x);  __stcs(o + 5 * WH, b.y);
    __stcs(o + 6 * WH, b.z);  __stcs(o + 7 * WH, b.w);
    __stcs(o + 8 * WH, v8);
}

extern "C" void kernel_launch(void* const* d_in, const int* in_sizes, int n_in,
                              void* d_out, int out_size) {
    // events = largest input; weights matched by size in declared order.
    int ie = 0;
    for (int i = 1; i < n_in; ++i)
        if (in_sizes[i] > in_sizes[ie]) ie = i;

    const int want[6] = {100, 100, 10000, 100, 100, 1};
    const float* wp[6] = {nullptr, nullptr, nullptr, nullptr, nullptr, nullptr};
    int wi = 0;
    for (int i = 0; i < n_in && wi < 6; ++i) {
        if (i == ie) continue;
        if (in_sizes[i] == want[wi])
            wp[wi++] = (const float*)d_in[i];
    }

    const float* events = (const float*)d_in[ie];
    int N = in_sizes[ie] / 5;
    float* out = (float*)d_out;

    // Zero scratch with a single driver memset node (~3 us). L2-warm after.
    void* scratch_ptr = nullptr;
    cudaGetSymbolAddress(&scratch_ptr, g_scratch);
    size_t scratch_bytes = (size_t)NCELLS * 9 * sizeof(float);  // A+B+S
    cudaMemsetAsync(scratch_ptr, 0, scratch_bytes, 0);

    // Staged + k-split LUT build.
    lut_kernel<<<LUT_BLOCKS, LUT_THREADS>>>(
        wp[0], wp[1], wp[2], wp[3], wp[4], wp[5]);

    int blocks = (N + 255) / 256;
    scatter_kernel<<<blocks, 256>>>(events, N);

    int tblocks = (NCELLS + 255) / 256;
    transpose_kernel<<<tblocks, 256>>>(out);
}

// round 16
// speedup vs baseline: 1.0579x; 1.0579x over previous
#include <cuda_runtime.h>
#include <cuda_bf16.h>

// Problem constants:
//   N events, H=256, W=336, B=8, C=9, HID=100
//   out: [B, 2C, H, W] float32
//   out idx = x + W*y + W*H*i + W*H*C*p01 + 2*W*H*C*b
#define HID        100
#define C_BINS     9
#define W_DIM      336
#define H_DIM      256
#define WH         (W_DIM * H_DIM)          // 86016
#define WHC        (WH * C_BINS)            // 774144
#define WHC2       (2 * WHC)                // 1548288
#define NCELLS     (16 * WH)                // (2b+p01) in [0,16) x pixel

// LUT over s in [-1,1]: 1025 knots, step 2/1024. Bin shift 0.125 = 64 steps.
#define LUT_SIZE     1025
#define LUT_SCALE    512.0f
#define BIN_STEP_IDX 64

#define LUT_THREADS  256
#define LUT_EPB      2                       // entries per block (4 warps each)
#define LUT_BLOCKS   513                     // ceil(1025/2)

// Single scratch region (one memset): [A: NCELLS float4][B: NCELLS float4][S: NCELLS float]
#define SCRATCH_F4   (2 * NCELLS)            // float4 count for A+B
__device__ float4 g_scratch[SCRATCH_F4 + NCELLS / 4 + 1];   // ~49.6 MB
__device__ float  g_lut[LUT_SIZE];

#define SA (g_scratch)
#define SB (g_scratch + NCELLS)
#define SS (reinterpret_cast<float*>(g_scratch + SCRATCH_F4))

__device__ __forceinline__ float leaky(float v) {
    return v >= 0.0f ? v : 0.1f * v;
}

// LUT build, k-split (R14-proven): each entry handled by 4 warps, each
// covering 25 of the 100 (linear) layer-2 k-terms; partials reduced in smem,
// then one warp applies leaky + w3 dot. 513 blocks cover all SMs; w2 fetches
// hit L2 after the first wave.
__global__ void __launch_bounds__(LUT_THREADS)
lut_kernel(const float* __restrict__ w1, const float* __restrict__ b1,
           const float* __restrict__ w2, const float* __restrict__ b2,
           const float* __restrict__ w3, const float* __restrict__ b3) {
    __shared__ float4 sm_a[LUT_EPB][4][25];

    const int tid  = threadIdx.x;
    const int lane = tid & 31;
    const int w    = tid >> 5;               // warp 0..7
    const int slot = w >> 2;                 // entry slot 0..1
    const int c    = w & 3;                  // k-chunk 0..3
    const int koff = 25 * c;

    int entry = blockIdx.x * LUT_EPB + slot;
    if (entry > LUT_SIZE - 1) entry = LUT_SIZE - 1;   // dup work, same value

    const float s = -1.0f + (float)entry * (2.0f / 1024.0f);

    // Each of lanes 0..24 computes h1 for one k in this warp's chunk.
    float h_l = 0.0f;
    if (lane < 25)
        h_l = leaky(fmaf(s, __ldg(w1 + koff + lane), __ldg(b1 + koff + lane)));

    // Each lane accumulates 4 output columns j = 4*jl .. 4*jl+3 over 25 k.
    const int jl = (lane < 25) ? lane : 24;
    float4 a = make_float4(0.f, 0.f, 0.f, 0.f);
    const float4* w2v = (const float4*)w2;   // w2[k][j], 25 float4 per k row

#pragma unroll
    for (int m = 0; m < 25; ++m) {
        float h = __shfl_sync(0xffffffffu, h_l, m);
        float4 wv = __ldg(w2v + (koff + m) * 25 + jl);
        a.x = fmaf(h, wv.x, a.x);
        a.y = fmaf(h, wv.y, a.y);
        a.z = fmaf(h, wv.z, a.z);
        a.w = fmaf(h, wv.w, a.w);
    }

    if (lane < 25)
        sm_a[slot][c][lane] = a;
    __syncthreads();

    // Finalize: one warp per entry (chunk 0 warps).
    if (c == 0) {
        float acc = 0.0f;
        if (lane < 25) {
            float4 a0 = sm_a[slot][0][lane];
            float4 a1 = sm_a[slot][1][lane];
            float4 a2 = sm_a[slot][2][lane];
            float4 a3 = sm_a[slot][3][lane];
            float4 bb = __ldg((const float4*)b2 + lane);
            float4 t;
            t.x = a0.x + a1.x + a2.x + a3.x + bb.x;
            t.y = a0.y + a1.y + a2.y + a3.y + bb.y;
            t.z = a0.z + a1.z + a2.z + a3.z + bb.z;
            t.w = a0.w + a1.w + a2.w + a3.w + bb.w;
            float4 w3v = __ldg((const float4*)w3 + lane);
            acc  = w3v.x * leaky(t.x);
            acc += w3v.y * leaky(t.y);
            acc += w3v.z * leaky(t.z);
            acc += w3v.w * leaky(t.w);
        }
        acc += __shfl_xor_sync(0xffffffffu, acc, 16);
        acc += __shfl_xor_sync(0xffffffffu, acc, 8);
        acc += __shfl_xor_sync(0xffffffffu, acc, 4);
        acc += __shfl_xor_sync(0xffffffffu, acc, 2);
        acc += __shfl_xor_sync(0xffffffffu, acc, 1);
        if (lane == 0)
            g_lut[entry] = acc + __ldg(b3);
    }
}

// Scatter into SoA scratch: red.v4 (bins 0-3) + red.v4 (bins 4-7) + red (bin 8).
// Event loads use ld.global.cs (evict-first) so the 40 MB event stream does
// not evict the L2-resident scratch lines the REDs RMW against.
__global__ void __launch_bounds__(256)
scatter_kernel(const float* __restrict__ ev, int N) {
    int n = blockIdx.x * blockDim.x + threadIdx.x;
    if (n >= N) return;

    const float* e = ev + 5ll * n;
    float xf = __ldcs(e + 0), yf = __ldcs(e + 1), t = __ldcs(e + 2);
    float pf = __ldcs(e + 3), bf = __ldcs(e + 4);

    int p01  = (pf > 0.0f) ? 1 : 0;
    int cell = ((int)bf * 2 + p01) * WH + (int)xf + W_DIM * (int)yf;

    float u0 = fmaf(t, LUT_SCALE, LUT_SCALE);
    int   i0 = (int)u0;
    if (i0 > LUT_SIZE - 2) i0 = LUT_SIZE - 2;
    float fr = u0 - (float)i0;

    float v[C_BINS];
#pragma unroll
    for (int i = 0; i < C_BINS; ++i) {
        int base = i0 - BIN_STEP_IDX * i;
        float v0 = g_lut[base];
        float v1 = g_lut[base + 1];
        v[i] = t * fmaf(fr, v1 - v0, v0);
    }

    asm volatile("red.global.add.v4.f32 [%0], {%1,%2,%3,%4};"
                 :: "l"(SA + cell), "f"(v[0]), "f"(v[1]), "f"(v[2]), "f"(v[3])
                 : "memory");
    asm volatile("red.global.add.v4.f32 [%0], {%1,%2,%3,%4};"
                 :: "l"(SB + cell), "f"(v[4]), "f"(v[5]), "f"(v[6]), "f"(v[7])
                 : "memory");
    atomicAdd(SS + cell, v[8]);
}

// Transpose SoA scratch -> reference output layout. Read-once scratch via
// ld.global.cs; out stores via st.global.cs (no L2 allocate churn).
__global__ void __launch_bounds__(256)
transpose_kernel(float* __restrict__ out) {
    int c = blockIdx.x * blockDim.x + threadIdx.x;
    if (c >= NCELLS) return;

    int q  = c % WH;
    int pb = c / WH;                 // 2*b + p01
    float4 a = __ldcs(SA + c);
    float4 b = __ldcs(SB + c);
    float  v8 = __ldcs(SS + c);

    float* o = out + q + (pb & 1) * WHC + (pb >> 1) * WHC2;
    __stcs(o + 0 * WH, a.x);  __stcs(o + 1 * WH, a.y);
    __stcs(o + 2 * WH, a.z);  __stcs(o + 3 * WH, a.w);
    __stcs(o + 4 * WH, b.x);  __stcs(o + 5 * WH, b.y);
    __stcs(o + 6 * WH, b.z);  __stcs(o + 7 * WH, b.w);
    __stcs(o + 8 * WH, v8);
}

extern "C" void kernel_launch(void* const* d_in, const int* in_sizes, int n_in,
                              void* d_out, int out_size) {
    // events = largest input; weights matched by size in declared order.
    int ie = 0;
    for (int i = 1; i < n_in; ++i)
        if (in_sizes[i] > in_sizes[ie]) ie = i;

    const int want[6] = {100, 100, 10000, 100, 100, 1};
    const float* wp[6] = {nullptr, nullptr, nullptr, nullptr, nullptr, nullptr};
    int wi = 0;
    for (int i = 0; i < n_in && wi < 6; ++i) {
        if (i == ie) continue;
        if (in_sizes[i] == want[wi])
            wp[wi++] = (const float*)d_in[i];
    }

    const float* events = (const float*)d_in[ie];
    int N = in_sizes[ie] / 5;
    float* out = (float*)d_out;

    // Zero scratch with a single driver memset node (~3 us). L2-warm after.
    void* scratch_ptr = nullptr;
    cudaGetSymbolAddress(&scratch_ptr, g_scratch);
    size_t scratch_bytes = (size_t)NCELLS * 9 * sizeof(float);  // A+B+S
    cudaMemsetAsync(scratch_ptr, 0, scratch_bytes, 0);

    // k-split LUT build (R14-proven fast variant).
    lut_kernel<<<LUT_BLOCKS, LUT_THREADS>>>(
        wp[0], wp[1], wp[2], wp[3], wp[4], wp[5]);

    int blocks = (N + 255) / 256;
    scatter_kernel<<<blocks, 256>>>(events, N);

    int tblocks = (NCELLS + 255) / 256;
    transpose_kernel<<<tblocks, 256>>>(out);
}